// round 7
// baseline (speedup 1.0000x reference)
#include <cuda_runtime.h>

#define BB 256
#define TT 64
#define NN 128
#define HH 512
#define G4 2048
#define KK 640          // N + H
#define NCTA 128

// ---------------- device scratch (static, allocation-free) ----------------
__device__ __align__(16) float g_z2[BB * NN * TT];   // (b,n,s) s-contiguous, 8 MB
__device__ __align__(16) float g_A[2][BB * KK];      // double-buffered: [wx(128) | h(512)] per b
__device__ __align__(16) float g_c[BB * HH];         // cell state
__device__ __align__(16) float g_Wc[KK * G4];        // combined weights, (k, jp) jp-fastest
__device__ __align__(16) float g_bias[G4];           // permuted b_ih + b_hh
__device__ unsigned g_bar;

// ---------------- math helpers ----------------
__device__ __forceinline__ float sigm(float x) {
    return 1.0f / (1.0f + __expf(-x));
}
__device__ __forceinline__ float tanh_acc(float x) {   // used in LSTM cell
    return 2.0f / (1.0f + __expf(-2.0f * x)) - 1.0f;
}
__device__ __forceinline__ float tanh_fast(float x) {  // MUFU.TANH: attention scores
    float y;
    asm("tanh.approx.f32 %0, %1;" : "=f"(y) : "f"(x));
    return y;
}

// packed f32x2 helpers (sm_100+): identical IEEE-rn rounding to scalar FFMA
__device__ __forceinline__ void fma2(unsigned long long& acc,
                                     unsigned long long a, unsigned long long b) {
    asm("fma.rn.f32x2 %0, %1, %2, %0;" : "+l"(acc) : "l"(a), "l"(b));
}
__device__ __forceinline__ unsigned long long dup2(float v) {
    unsigned long long r;
    asm("mov.b64 %0, {%1, %1};" : "=l"(r) : "f"(v));
    return r;
}
__device__ __forceinline__ void unpack2(float& lo, float& hi, unsigned long long v) {
    asm("mov.b64 {%0, %1}, %2;" : "=f"(lo), "=f"(hi) : "l"(v));
}

// ---------------- grid barrier (128 CTAs, all resident on 148 SMs) --------
// epoch-based: barrier e complete when g_bar >= e*NCTA (monotonic counter)
__device__ __forceinline__ void grid_sync(unsigned& epoch) {
    __syncthreads();
    if (threadIdx.x == 0) {
        ++epoch;
        __threadfence();                       // release prior global writes
        atomicAdd(&g_bar, 1u);                 // returnless -> RED
        unsigned need = epoch * NCTA;
        unsigned cur;
        do {
            asm volatile("ld.acquire.gpu.u32 %0, [%1];" : "=r"(cur) : "l"(&g_bar));
        } while (cur < need);
    }
    __syncthreads();
}

// ---------------- fused prep + z2 precompute -------------------------------
// blocks [0, 1024)   : z2[b,n,s] = sum_t dx[b,t,n]*W_a2[s,t] + b_a2[s]
// blocks [1024, 2048): permuted combined weights + zero state + barrier reset
__global__ void setup_kernel(const float* __restrict__ dx,
                             const float* __restrict__ W_a2,
                             const float* __restrict__ b_a2,
                             const float* __restrict__ W_ih,
                             const float* __restrict__ W_hh,
                             const float* __restrict__ b_ih,
                             const float* __restrict__ b_hh)
{
    if (blockIdx.x < 1024) {
        // ---- z2 part ----
        __shared__ float xs[TT][32];
        __shared__ float wa2[TT][65];
        int b  = blockIdx.x >> 2;
        int n0 = (blockIdx.x & 3) << 5;
        int tid = threadIdx.x;
        for (int i = tid; i < TT * 32; i += 256) {
            int t = i >> 5, j = i & 31;
            xs[t][j] = dx[(b * TT + t) * NN + n0 + j];
        }
        for (int i = tid; i < TT * TT; i += 256)
            wa2[i >> 6][i & 63] = W_a2[i];
        __syncthreads();
        #pragma unroll
        for (int p = 0; p < 8; ++p) {
            int id = p * 256 + tid;
            int s = id & 63, nj = id >> 6;
            float acc = b_a2[s];
            #pragma unroll 8
            for (int t = 0; t < TT; ++t)
                acc += xs[t][nj] * wa2[s][t];
            g_z2[(((b << 7) + n0 + nj) << 6) + s] = acc;
        }
    } else {
        // ---- prep part ----
        int idx = (blockIdx.x - 1024) * blockDim.x + threadIdx.x;
        const int stride = 1024 * 256;
        // jp = hj*4 + gate  (gate order i,f,g,o); k<128 -> W_ih, else W_hh
        for (int i = idx; i < KK * G4; i += stride) {
            int k  = i >> 11;
            int jp = i & 2047;
            int j  = (jp & 3) * HH + (jp >> 2);
            g_Wc[i] = (k < NN) ? W_ih[j * NN + k] : W_hh[j * HH + (k - NN)];
        }
        for (int i = idx; i < G4; i += stride) {
            int j = (i & 3) * HH + (i >> 2);
            g_bias[i] = b_ih[j] + b_hh[j];
        }
        for (int i = idx; i < BB * HH; i += stride) {
            int b = i >> 9, j = i & 511;
            g_c[i] = 0.0f;
            g_A[0][b * KK + NN + j] = 0.0f;
            g_A[1][b * KK + NN + j] = 0.0f;
        }
        if (idx == 0) g_bar = 0u;
    }
}

// ---------------- persistent recurrent kernel ------------------------------
// dynamic smem: this CTA's full W slice, [640][64] floats = 160 KB
extern __shared__ float Wsm[];

__global__ void __launch_bounds__(256, 1) lstm_kernel(
    const float* __restrict__ dx,
    const float* __restrict__ W_a1,
    const float* __restrict__ b_a1,
    const float* __restrict__ W_a3,
    const float* __restrict__ b_a3,
    float* __restrict__ out)
{
    __shared__ __align__(16) float z1s[2][64];
    __shared__ __align__(16) float es[2][128];
    __shared__ __align__(16) float wa3s[64];
    __shared__ __align__(16) float ba1s[64];
    __shared__ __align__(16) float As[2][32][68];   // double-buffered A tile, [k][b], pad 68

    const int tid  = threadIdx.x;
    const int cta  = blockIdx.x;
    const int lane = tid & 31;
    const int warp = tid >> 5;
    const int tx   = tid & 15;        // jp micro-tile
    const int ty   = tid >> 4;        // b micro-tile

    if (tid < 64) { wa3s[tid] = W_a3[tid]; ba1s[tid] = b_a1[tid]; }
    const float ba3 = b_a3[0];
    unsigned epoch = 0u;

    // phase-B tile assignment: 4 b-groups x 32 gate-slices
    const int bg  = cta >> 5;
    const int jg  = cta & 31;
    const int b0  = bg << 6;
    const int jp0 = jg << 6;
    const int hj  = (jg << 4) + tx;           // h index this thread owns
    const float bs0 = g_bias[jp0 + (tx << 2) + 0];
    const float bs1 = g_bias[jp0 + (tx << 2) + 1];
    const float bs2 = g_bias[jp0 + (tx << 2) + 2];
    const float bs3 = g_bias[jp0 + (tx << 2) + 3];

    // staging indices for A tiles (GEMM)
    const int lk = tid & 31;          // k within tile
    const int lb = tid >> 5;          // b base within tile (stride 8)

    // A2 mapping: 4 n per warp-iteration, 8 lanes per n, 8 s per lane
    const int nsub = lane >> 3;       // which of 4 n this lane serves
    const int sidx = (lane & 7) << 3; // s base for this lane (0..56 step 8)

    // load this CTA's W slice into shared, once: Wsm[k][j] = g_Wc[k*2048 + jp0 + j]
    {
        const int nf4 = KK * 64 / 4;           // 10240 float4
        float4* dst = (float4*)Wsm;
        for (int i = tid; i < nf4; i += 256) {
            int k = i >> 4, c4 = i & 15;
            dst[i] = *(const float4*)&g_Wc[k * G4 + jp0 + (c4 << 2)];
        }
    }

    // phase-A batch assignment: 2 b per CTA
    const int ba = cta << 1;
    __syncthreads();

    for (int t = 0; t < TT; ++t) {
        const float* Acur = g_A[t & 1];
        float*       Anxt = g_A[(t & 1) ^ 1];

        // ===== Phase A1: z1[b,s] = [h|c] . W_a1[s] + b_a1[s], for b=ba,ba+1 =====
        {
            const float4* h0p = (const float4*)(Acur + ba * KK + NN) + lane;
            const float4* h1p = (const float4*)(Acur + (ba + 1) * KK + NN) + lane;
            const float4* c0p = (const float4*)(g_c + (ba << 9)) + lane;
            const float4* c1p = (const float4*)(g_c + ((ba + 1) << 9)) + lane;
            // hoist h,c into registers once (16 float4), reused across all 8 s
            float4 xh0[4], xh1[4], xc0[4], xc1[4];
            #pragma unroll
            for (int k = 0; k < 4; ++k) {
                xh0[k] = __ldcg(h0p + k * 32);
                xh1[k] = __ldcg(h1p + k * 32);
                xc0[k] = __ldcg(c0p + k * 32);
                xc1[k] = __ldcg(c1p + k * 32);
            }
            #pragma unroll
            for (int q = 0; q < 8; ++q) {
                int s = warp + (q << 3);
                const float4* wh = (const float4*)(W_a1 + (s << 10)) + lane;
                const float4* wc = (const float4*)(W_a1 + (s << 10) + 512) + lane;
                float a0 = 0.f, a1 = 0.f;
                #pragma unroll
                for (int k = 0; k < 4; ++k) {
                    float4 w = __ldcs(wh + k * 32);      // streaming: keep L1 for z2
                    a0 += w.x * xh0[k].x + w.y * xh0[k].y + w.z * xh0[k].z + w.w * xh0[k].w;
                    a1 += w.x * xh1[k].x + w.y * xh1[k].y + w.z * xh1[k].z + w.w * xh1[k].w;
                }
                #pragma unroll
                for (int k = 0; k < 4; ++k) {
                    float4 w = __ldcs(wc + k * 32);      // streaming: keep L1 for z2
                    a0 += w.x * xc0[k].x + w.y * xc0[k].y + w.z * xc0[k].z + w.w * xc0[k].w;
                    a1 += w.x * xc1[k].x + w.y * xc1[k].y + w.z * xc1[k].z + w.w * xc1[k].w;
                }
                #pragma unroll
                for (int d = 16; d > 0; d >>= 1) {
                    a0 += __shfl_xor_sync(0xffffffffu, a0, d);
                    a1 += __shfl_xor_sync(0xffffffffu, a1, d);
                }
                if (lane == 0) {
                    z1s[0][s] = a0 + ba1s[s];
                    z1s[1][s] = a1 + ba1s[s];
                }
            }
        }
        __syncthreads();

        // ===== Phase A2: e[b,n] = sum_s tanh(z1+z2)*W_a3[s] + b_a3 =====
        // 4 n per warp-iteration: 8 lanes per n, each lane covers 8 s (2 float4)
        // z2 is immutable during this kernel (written by setup_kernel, prior
        // launch, L1 flushed at boundary) and re-read every step -> L1-cache it.
        {
            float4 z1a[2][2], wa[2];
            z1a[0][0] = *(const float4*)&z1s[0][sidx];
            z1a[0][1] = *(const float4*)&z1s[0][sidx + 4];
            z1a[1][0] = *(const float4*)&z1s[1][sidx];
            z1a[1][1] = *(const float4*)&z1s[1][sidx + 4];
            wa[0] = *(const float4*)&wa3s[sidx];
            wa[1] = *(const float4*)&wa3s[sidx + 4];
            #pragma unroll
            for (int gi = 0; gi < 4; ++gi) {
                int n = ((gi << 3) + warp) * 4 + nsub;   // 4 distinct n per warp
                #pragma unroll
                for (int bl = 0; bl < 2; ++bl) {
                    int b = ba + bl;
                    const float4* z2p = (const float4*)(g_z2 + (((b << 7) + n) << 6) + sidx);
                    float4 q0 = __ldg(z2p);
                    float4 q1 = __ldg(z2p + 1);
                    float v = tanh_fast(z1a[bl][0].x + q0.x) * wa[0].x
                            + tanh_fast(z1a[bl][0].y + q0.y) * wa[0].y
                            + tanh_fast(z1a[bl][0].z + q0.z) * wa[0].z
                            + tanh_fast(z1a[bl][0].w + q0.w) * wa[0].w
                            + tanh_fast(z1a[bl][1].x + q1.x) * wa[1].x
                            + tanh_fast(z1a[bl][1].y + q1.y) * wa[1].y
                            + tanh_fast(z1a[bl][1].z + q1.z) * wa[1].z
                            + tanh_fast(z1a[bl][1].w + q1.w) * wa[1].w;
                    // reduce within each 8-lane group (lane>>3 preserved)
                    #pragma unroll
                    for (int d = 4; d > 0; d >>= 1)
                        v += __shfl_xor_sync(0xffffffffu, v, d);
                    if ((lane & 7) == 0) es[bl][n] = v + ba3;
                }
            }
        }
        __syncthreads();

        // ===== softmax over n + wx = w * x_t (warps 0,1) =====
        if (warp < 2) {
            int b = ba + warp;
            float v0 = es[warp][lane],      v1 = es[warp][lane + 32];
            float v2 = es[warp][lane + 64], v3 = es[warp][lane + 96];
            float m = fmaxf(fmaxf(v0, v1), fmaxf(v2, v3));
            #pragma unroll
            for (int d = 16; d > 0; d >>= 1)
                m = fmaxf(m, __shfl_xor_sync(0xffffffffu, m, d));
            float e0 = __expf(v0 - m), e1 = __expf(v1 - m);
            float e2 = __expf(v2 - m), e3 = __expf(v3 - m);
            float s = e0 + e1 + e2 + e3;
            #pragma unroll
            for (int d = 16; d > 0; d >>= 1)
                s += __shfl_xor_sync(0xffffffffu, s, d);
            float inv = 1.0f / s;
            const float* xr = dx + (((b << 6) + t) << 7);
            float* wxr = (float*)Acur + (size_t)b * KK;
            __stcg(&wxr[lane],      e0 * inv * xr[lane]);
            __stcg(&wxr[lane + 32], e1 * inv * xr[lane + 32]);
            __stcg(&wxr[lane + 64], e2 * inv * xr[lane + 64]);
            __stcg(&wxr[lane + 96], e3 * inv * xr[lane + 96]);
        }
        grid_sync(epoch);   // wx + (h,c from prev step) globally visible everywhere

        // ===== Phase B: gates tile [64 b x 64 jp] = A[64x640] @ Wc[640x64] =====
        // packed f32x2: acc2[pair][j] = (gates[b_lo][j], gates[b_hi][j])
        unsigned long long acc2[2][4];
        #pragma unroll
        for (int i = 0; i < 2; ++i)
            #pragma unroll
            for (int j = 0; j < 4; ++j) acc2[i][j] = 0ull;

        // prefetch tile 0 into registers
        float r[8];
        #pragma unroll
        for (int q = 0; q < 8; ++q)
            r[q] = __ldcg(&Acur[(size_t)(b0 + lb + (q << 3)) * KK + lk]);

        for (int kt = 0; kt < 20; ++kt) {
            const int cur = kt & 1;
            // commit prefetched tile kt to smem
            #pragma unroll
            for (int q = 0; q < 8; ++q)
                As[cur][lk][lb + (q << 3)] = r[q];
            __syncthreads();
            // prefetch tile kt+1 (latency hidden behind compute below)
            if (kt < 19) {
                int k0n = (kt + 1) << 5;
                #pragma unroll
                for (int q = 0; q < 8; ++q)
                    r[q] = __ldcg(&Acur[(size_t)(b0 + lb + (q << 3)) * KK + k0n + lk]);
            }
            const int k0 = kt << 5;
            #pragma unroll
            for (int k = 0; k < 32; ++k) {
                float4 av = *(const float4*)&As[cur][k][ty << 2];      // 2 b-pairs
                float4 wv = *(const float4*)&Wsm[(k0 + k) * 64 + (tx << 2)];
                unsigned long long ap0 = ((const unsigned long long*)&av)[0];
                unsigned long long ap1 = ((const unsigned long long*)&av)[1];
                unsigned long long w0 = dup2(wv.x), w1 = dup2(wv.y);
                unsigned long long w2 = dup2(wv.z), w3 = dup2(wv.w);
                fma2(acc2[0][0], ap0, w0); fma2(acc2[0][1], ap0, w1);
                fma2(acc2[0][2], ap0, w2); fma2(acc2[0][3], ap0, w3);
                fma2(acc2[1][0], ap1, w0); fma2(acc2[1][1], ap1, w1);
                fma2(acc2[1][2], ap1, w2); fma2(acc2[1][3], ap1, w3);
            }
            // no second sync needed: iteration kt+1 stores into the OTHER buffer,
            // whose last readers (compute of kt-1) are ordered before sync(kt)
        }

        // ===== LSTM pointwise (i,f,g,o are this thread's 4 consecutive jp) ====
        #pragma unroll
        for (int pr = 0; pr < 2; ++pr) {
            float gi_l, gi_h, gf_l, gf_h, gg_l, gg_h, go_l, go_h;
            unpack2(gi_l, gi_h, acc2[pr][0]);
            unpack2(gf_l, gf_h, acc2[pr][1]);
            unpack2(gg_l, gg_h, acc2[pr][2]);
            unpack2(go_l, go_h, acc2[pr][3]);
            #pragma unroll
            for (int lh = 0; lh < 2; ++lh) {
                int b = b0 + (ty << 2) + (pr << 1) + lh;
                float gi = (lh ? gi_h : gi_l) + bs0;
                float gf = (lh ? gf_h : gf_l) + bs1;
                float gg = (lh ? gg_h : gg_l) + bs2;
                float go = (lh ? go_h : go_l) + bs3;
                float c_old = __ldcg(&g_c[(b << 9) + hj]);
                float cn = sigm(gf) * c_old + sigm(gi) * tanh_acc(gg);
                float hn = sigm(go) * tanh_acc(cn);
                __stcg(&g_c[(b << 9) + hj], cn);
                __stcg(&Anxt[(size_t)b * KK + NN + hj], hn);
                __stcs(&out[(((b << 6) + t) << 9) + hj], hn);
            }
        }
        grid_sync(epoch);   // h,c visible for next step's phase A
    }
}

// ---------------- launch ----------------
extern "C" void kernel_launch(void* const* d_in, const int* in_sizes, int n_in,
                              void* d_out, int out_size)
{
    const float* dx   = (const float*)d_in[0];
    const float* W_a1 = (const float*)d_in[1];
    const float* b_a1 = (const float*)d_in[2];
    const float* W_a2 = (const float*)d_in[3];
    const float* b_a2 = (const float*)d_in[4];
    const float* W_a3 = (const float*)d_in[5];
    const float* b_a3 = (const float*)d_in[6];
    const float* W_ih = (const float*)d_in[7];
    const float* W_hh = (const float*)d_in[8];
    const float* b_ih = (const float*)d_in[9];
    const float* b_hh = (const float*)d_in[10];
    float* out = (float*)d_out;

    const int wsm_bytes = KK * 64 * sizeof(float);   // 160 KB dynamic smem
    cudaFuncSetAttribute(lstm_kernel, cudaFuncAttributeMaxDynamicSharedMemorySize, wsm_bytes);

    setup_kernel<<<2048, 256>>>(dx, W_a2, b_a2, W_ih, W_hh, b_ih, b_hh);
    lstm_kernel<<<NCTA, 256, wsm_bytes>>>(dx, W_a1, b_a1, W_a3, b_a3, out);
}